// round 12
// baseline (speedup 1.0000x reference)
#include <cuda_runtime.h>
#include <cuda_bf16.h>
#include <cstdint>

#define NUM_TAGS 48
#define SEQ_LEN  512
#define BATCH    1024
#define NB       8                   // batches per warp (MMA N)
#define NCTA     (BATCH / NB)        // 128 CTAs, 1 warp each
#define CHUNK    8
#define NCHUNK   (SEQ_LEN / CHUNK)   // 64
#define EPAD     52                  // padded floats per (t,n) emission row
#define WPAD     52                  // padded floats per batch row of W^T

__device__ float    g_nll[BATCH];
__device__ unsigned g_count = 0;

__device__ __forceinline__ uint32_t f2tf(float f) {
    uint32_t r;
    asm("cvt.rna.tf32.f32 %0, %1;" : "=r"(r) : "f"(f));
    return r;
}

__device__ __forceinline__ void mma_tf32(float* d,
    uint32_t a0, uint32_t a1, uint32_t a2, uint32_t a3,
    uint32_t b0, uint32_t b1)
{
    asm volatile(
        "mma.sync.aligned.m16n8k8.row.col.f32.tf32.tf32.f32 "
        "{%0,%1,%2,%3}, {%4,%5,%6,%7}, {%8,%9}, {%0,%1,%2,%3};"
        : "+f"(d[0]), "+f"(d[1]), "+f"(d[2]), "+f"(d[3])
        : "r"(a0), "r"(a1), "r"(a2), "r"(a3), "r"(b0), "r"(b1));
}

__device__ __forceinline__ void cp16(uint32_t saddr, const void* g) {
    asm volatile("cp.async.cg.shared.global [%0], [%1], 16;" :: "r"(saddr), "l"(g));
}

// One warp (one CTA) per 8 batch elements. Forward recursion as tensor-core
// GEMM: W'(48x8) = E^T(48x48) @ W(48x8) via 18 mma.sync m16n8k8 tf32, then
// elementwise * exp(e_t) in fp32, cvt to tf32, smem round-trip.
// Thread map (lane = 4*g + tig, g=lane>>2, tig=lane&3):
//   A frag (mt,kk): a0=(16mt+g, 8kk+tig) a1=(+8,) a2=(,+4) a3=(+8,+4), A=E^T
//   B frag (kk):    b0=W[8kk+tig][g]  b1=W[8kk+tig+4][g]
//   D (mt):         d0=(16mt+g, 2tig) d1=(,2tig+1) d2=(+8,2tig) d3=(+8,2tig+1)
__global__ __launch_bounds__(32)
void crf_mma_kernel(const float* __restrict__ emissions,
                    const float* __restrict__ transitions,
                    const int*   __restrict__ tags,
                    const int*   __restrict__ mask,
                    float*       __restrict__ out)
{
    const int lane = threadIdx.x;
    const int g    = lane >> 2;   // 0..7
    const int tig  = lane & 3;    // 0..3
    const int b8   = blockIdx.x * NB;

    __shared__ __align__(16) float    sem[3][CHUNK][NB][EPAD]; // staged emissions
    __shared__ __align__(16) uint32_t sW[2][NB][WPAD];         // W^T, tf32 bits
    __shared__ float sscore[NB], sC[NB], sCarry[NB];

    const float* em0   = emissions + (size_t)b8 * SEQ_LEN * NUM_TAGS;
    const int*   tagsg = tags + (size_t)b8 * SEQ_LEN;
    const int*   maskg = mask + (size_t)b8 * SEQ_LEN;

    // --- stage emission chunks 0,1 (two pending cp.async groups) --------------
    #pragma unroll
    for (int pc = 0; pc < 2; pc++) {
        uint32_t dstb = (uint32_t)__cvta_generic_to_shared(&sem[pc][0][0][0]);
        #pragma unroll
        for (int i = lane; i < CHUNK * NB * 12; i += 32) {
            int row = i / 12, part = i % 12;
            int u = row >> 3, n = row & 7;
            const float* src = em0 + ((size_t)n * SEQ_LEN + pc * CHUNK + u) * NUM_TAGS + part * 4;
            cp16(dstb + (uint32_t)(((u * NB + n) * EPAD + part * 4) * 4), src);
        }
        asm volatile("cp.async.commit_group;");
    }

    // --- gold-path scores (long; overlaps staging latency) ---------------------
    for (int bb = 0; bb < NB; bb++) {
        float r = 0.0f;
        for (int t = 1 + lane; t < SEQ_LEN; t += 32) {
            int tc = tagsg[bb * SEQ_LEN + t];
            int tp = tagsg[bb * SEQ_LEN + t - 1];
            if (maskg[bb * SEQ_LEN + t])
                r += em0[((size_t)bb * SEQ_LEN + t) * NUM_TAGS + tc]
                   + transitions[tp * NUM_TAGS + tc];
        }
        #pragma unroll
        for (int off = 16; off; off >>= 1)
            r += __shfl_xor_sync(0xffffffffu, r, off);
        if (lane == 0) {
            int t0 = tagsg[bb * SEQ_LEN];
            sscore[bb] = r + em0[(size_t)bb * SEQ_LEN * NUM_TAGS + t0];
        }
    }

    // --- A fragments: E^T = exp(T)^T in tf32, 3 m-tiles x 6 k-tiles ------------
    uint32_t A[3][6][4];
    #pragma unroll
    for (int mt = 0; mt < 3; mt++)
        #pragma unroll
        for (int kk = 0; kk < 6; kk++) {
            int i = 8 * kk + tig, j = 16 * mt + g;
            A[mt][kk][0] = f2tf(__expf(transitions[(i    ) * NUM_TAGS + j    ]));
            A[mt][kk][1] = f2tf(__expf(transitions[(i    ) * NUM_TAGS + j + 8]));
            A[mt][kk][2] = f2tf(__expf(transitions[(i + 4) * NUM_TAGS + j    ]));
            A[mt][kk][3] = f2tf(__expf(transitions[(i + 4) * NUM_TAGS + j + 8]));
        }

    // --- init W^T: only tag 0 live ----------------------------------------------
    for (int i = lane; i < NB * WPAD; i += 32) {
        int n = i / WPAD, j = i % WPAD;
        sW[0][n][j] = (j == 0) ? 0x3F800000u : 0u;
    }
    __syncwarp();

    // --- forward recursion -------------------------------------------------------
    float C[2]  = {0.0f, 0.0f};     // per-batch log-scale, n = 2tig, 2tig+1
    float ci[2] = {1.0f, 1.0f};     // pending renorm scale

    for (int c = 0; c < NCHUNK; c++) {
        if (c + 2 < NCHUNK) {
            uint32_t dstb = (uint32_t)__cvta_generic_to_shared(&sem[(c + 2) % 3][0][0][0]);
            #pragma unroll
            for (int i = lane; i < CHUNK * NB * 12; i += 32) {
                int row = i / 12, part = i % 12;
                int u = row >> 3, n = row & 7;
                const float* src = em0 + ((size_t)n * SEQ_LEN + (c + 2) * CHUNK + u) * NUM_TAGS + part * 4;
                cp16(dstb + (uint32_t)(((u * NB + n) * EPAD + part * 4) * 4), src);
            }
        }
        asm volatile("cp.async.commit_group;");
        asm volatile("cp.async.wait_group 2;");
        __syncwarp();

        const float (*eb)[NB][EPAD] = sem[c % 3];

        // uniform mask check for this chunk (64 values, 2 per lane)
        int mm0 = maskg[(lane >> 2) * SEQ_LEN + c * CHUNK + 2 * (lane & 3)];
        int mm1 = maskg[(lane >> 2) * SEQ_LEN + c * CHUNK + 2 * (lane & 3) + 1];
        const bool mall = __all_sync(0xffffffffu, (mm0 != 0) && (mm1 != 0));

        if (!mall) {
            // pre-apply pending scale to W in smem (slow path only)
            #pragma unroll
            for (int mt = 0; mt < 3; mt++)
                #pragma unroll
                for (int hh = 0; hh < 2; hh++)
                    #pragma unroll
                    for (int rr = 0; rr < 2; rr++) {
                        int j = 16 * mt + g + 8 * hh, n = 2 * tig + rr;
                        float v = __uint_as_float(sW[0][n][j]) * ci[rr];
                        sW[0][n][j] = f2tf(v);
                    }
            ci[0] = 1.0f; ci[1] = 1.0f;
            __syncwarp();
        }

        #pragma unroll
        for (int u = 0; u < CHUNK; u++) {
            const int rb = u & 1, wb = rb ^ 1;

            // emission exps (off-chain; fold pending scale at u==0)
            float ex[3][2][2];
            #pragma unroll
            for (int mt = 0; mt < 3; mt++)
                #pragma unroll
                for (int hh = 0; hh < 2; hh++)
                    #pragma unroll
                    for (int rr = 0; rr < 2; rr++) {
                        float e = eb[u][2 * tig + rr][16 * mt + g + 8 * hh];
                        float v = __expf(e);
                        if (u == 0) v *= ci[rr];
                        ex[mt][hh][rr] = v;
                    }

            // B fragments from W^T
            uint32_t bfr[6][2];
            #pragma unroll
            for (int kk = 0; kk < 6; kk++) {
                bfr[kk][0] = sW[rb][g][8 * kk + tig];
                bfr[kk][1] = sW[rb][g][8 * kk + tig + 4];
            }

            // 6 independent accumulation chains (3 m-tiles x 2 k-halves), 3 deep
            float acc[3][2][4] = {};
            #pragma unroll
            for (int k2 = 0; k2 < 3; k2++)
                #pragma unroll
                for (int mt = 0; mt < 3; mt++)
                    #pragma unroll
                    for (int hf = 0; hf < 2; hf++)
                        mma_tf32(acc[mt][hf],
                                 A[mt][hf * 3 + k2][0], A[mt][hf * 3 + k2][1],
                                 A[mt][hf * 3 + k2][2], A[mt][hf * 3 + k2][3],
                                 bfr[hf * 3 + k2][0], bfr[hf * 3 + k2][1]);

            // scale by exp(e), convert to tf32, store (mask-select in slow path)
            if (mall) {
                #pragma unroll
                for (int mt = 0; mt < 3; mt++) {
                    #pragma unroll
                    for (int hh = 0; hh < 2; hh++)
                        #pragma unroll
                        for (int rr = 0; rr < 2; rr++) {
                            float d = acc[mt][0][2 * hh + rr] + acc[mt][1][2 * hh + rr];
                            int j = 16 * mt + g + 8 * hh, n = 2 * tig + rr;
                            sW[wb][n][j] = f2tf(d * ex[mt][hh][rr]);
                        }
                }
            } else {
                int m0 = maskg[(2 * tig    ) * SEQ_LEN + c * CHUNK + u];
                int m1 = maskg[(2 * tig + 1) * SEQ_LEN + c * CHUNK + u];
                #pragma unroll
                for (int mt = 0; mt < 3; mt++) {
                    #pragma unroll
                    for (int hh = 0; hh < 2; hh++)
                        #pragma unroll
                        for (int rr = 0; rr < 2; rr++) {
                            float d = acc[mt][0][2 * hh + rr] + acc[mt][1][2 * hh + rr];
                            int j = 16 * mt + g + 8 * hh, n = 2 * tig + rr;
                            uint32_t oldb = sW[rb][n][j];
                            uint32_t newb = f2tf(d * ex[mt][hh][rr]);
                            sW[wb][n][j] = ((rr == 0 ? m0 : m1) != 0) ? newb : oldb;
                        }
                }
            }
            __syncwarp();
        }

        // lazy per-batch renorm: s_n = W[0][n] (> 0 always); exact once logged
        #pragma unroll
        for (int rr = 0; rr < 2; rr++) {
            float s = __uint_as_float(sW[0][2 * tig + rr][0]);
            C[rr] += __logf(s);
            ci[rr] = __fdividef(1.0f, s);
        }
    }

    // --- publish per-batch C / carry (lanes 0..3 cover all n) --------------------
    if (g == 0) {
        sC[2 * tig]         = C[0];
        sC[2 * tig + 1]     = C[1];
        sCarry[2 * tig]     = ci[0];
        sCarry[2 * tig + 1] = ci[1];
    }
    __syncwarp();

    // --- logZ_n = C_n + log( (sum_j W[j][n]) * ci_n );  NLL ------------------------
    {
        int n = lane >> 2, seg = lane & 3;
        float p = 0.0f;
        #pragma unroll
        for (int j = seg * 12; j < seg * 12 + 12; j++)
            p += __uint_as_float(sW[0][n][j]);
        p += __shfl_xor_sync(0xffffffffu, p, 1);
        p += __shfl_xor_sync(0xffffffffu, p, 2);
        if (seg == 0) {
            float logZ = sC[n] + __logf(p * sCarry[n]);
            g_nll[b8 + n] = logZ - sscore[n];
        }
    }

    // --- fused mean-reduce: last CTA does the deterministic sum --------------------
    unsigned done = 0;
    if (lane == 0) {
        __threadfence();
        done = atomicAdd(&g_count, 1u);
    }
    done = __shfl_sync(0xffffffffu, done, 0);
    if (done == NCTA - 1) {
        __threadfence();
        float r = 0.0f;
        #pragma unroll
        for (int i = lane; i < BATCH; i += 32)
            r += __ldcg(&g_nll[i]);
        #pragma unroll
        for (int off = 16; off; off >>= 1)
            r += __shfl_xor_sync(0xffffffffu, r, off);
        if (lane == 0) {
            out[0] = r * (1.0f / (float)BATCH);
            g_count = 0;   // reset for next graph replay
        }
    }
}

extern "C" void kernel_launch(void* const* d_in, const int* in_sizes, int n_in,
                              void* d_out, int out_size)
{
    const float* emissions   = (const float*)d_in[0];
    const float* transitions = (const float*)d_in[1];
    const int*   tags        = (const int*)d_in[2];
    const int*   mask        = (const int*)d_in[3];
    float*       out         = (float*)d_out;

    crf_mma_kernel<<<NCTA, 32>>>(emissions, transitions, tags, mask, out);
}

// round 13
// speedup vs baseline: 1.2707x; 1.2707x over previous
#include <cuda_runtime.h>
#include <cuda_bf16.h>
#include <cstdint>

#define NUM_TAGS 48
#define SEQ_LEN  512
#define BATCH    1024
#define NB       8
#define NGRP     (BATCH / NB)        // 128 batch-groups
#define CHUNK    8
#define HALFLEN  256
#define NCH      (HALFLEN / CHUNK)   // 32 chunks per half
#define EPAD     52

__device__ float    g_vecF[NGRP][NUM_TAGS][NB];
__device__ float    g_vecB[NGRP][NUM_TAGS][NB];
__device__ float    g_C2[NGRP][2][NB];
__device__ float    g_sc2[NGRP][2][NB];
__device__ float    g_nll[BATCH];
__device__ unsigned g_pair[NGRP];
__device__ unsigned g_count = 0;

__device__ __forceinline__ uint32_t f2tf(float f) {
    uint32_t r;
    asm("cvt.rna.tf32.f32 %0, %1;" : "=r"(r) : "f"(f));
    return r;
}

__device__ __forceinline__ void mma_tf32(float* d,
    uint32_t a0, uint32_t a1, uint32_t a2, uint32_t a3,
    uint32_t b0, uint32_t b1)
{
    asm volatile(
        "mma.sync.aligned.m16n8k8.row.col.f32.tf32.tf32.f32 "
        "{%0,%1,%2,%3}, {%4,%5,%6,%7}, {%8,%9}, {%0,%1,%2,%3};"
        : "+f"(d[0]), "+f"(d[1]), "+f"(d[2]), "+f"(d[3])
        : "r"(a0), "r"(a1), "r"(a2), "r"(a3), "r"(b0), "r"(b1));
}

__device__ __forceinline__ void cp16(uint32_t saddr, const void* g) {
    asm volatile("cp.async.cg.shared.global [%0], [%1], 16;" :: "r"(saddr), "l"(g));
}

// grid = 2*NGRP single-warp CTAs. bid>>1 = batch-group (8 batches), bid&1 = half
// (0: forward t=[0,256), 1: backward t=[256,512) via transpose recursion).
// Per step: W'(48x8) = A(48x48) @ B(48x8) with 18 mma.sync m16n8k8 tf32.
// fwd: A=E^T, elementwise *exp(e_t) AFTER mma. bwd: A=E, exp(e_t) applied to B
// BEFORE mma. Raw fp32 bits fed as tf32 (truncation) — no in-loop CVTs.
// Fragment maps identical to the round-12 kernel (validated at 1e-6).
__global__ __launch_bounds__(32)
void crf_mma2_kernel(const float* __restrict__ emissions,
                     const float* __restrict__ transitions,
                     const int*   __restrict__ tags,
                     const int*   __restrict__ mask,
                     float*       __restrict__ out)
{
    const int lane = threadIdx.x;
    const int g    = lane >> 2;   // 0..7
    const int tig  = lane & 3;    // 0..3
    const int grp  = blockIdx.x >> 1;
    const int half = blockIdx.x & 1;
    const int b8   = grp * NB;

    __shared__ __align__(16) float sem[3][CHUNK * NB * EPAD]; // raw emissions
    __shared__ __align__(16) float sW[2][NUM_TAGS][NB];       // state tile
    __shared__ float sCi[NB];

    const float* em0   = emissions + (size_t)b8 * SEQ_LEN * NUM_TAGS;
    const int*   tagsg = tags + (size_t)b8 * SEQ_LEN;
    const int*   maskg = mask + (size_t)b8 * SEQ_LEN;

    // chunk c covers t = tb..tb+7; fwd ascends, bwd descends over chunks
    #define TBASE(c) (half == 0 ? (c) * CHUNK : (SEQ_LEN - CHUNK) - (c) * CHUNK)

    // --- stage chunks 0,1 ---------------------------------------------------
    #pragma unroll
    for (int pc = 0; pc < 2; pc++) {
        uint32_t dstb = (uint32_t)__cvta_generic_to_shared(&sem[pc][0]);
        int tb = TBASE(pc);
        for (int i = lane; i < CHUNK * NB * 12; i += 32) {
            int row = i / 12, part = i % 12;
            int u = row >> 3, n = row & 7;
            cp16(dstb + (uint32_t)(((u * NB + n) * EPAD + part * 4) * 4),
                 em0 + ((size_t)n * SEQ_LEN + tb + u) * NUM_TAGS + part * 4);
        }
        asm volatile("cp.async.commit_group;");
    }

    // --- gold-path scores for this half (overlaps staging) -------------------
    {
        const int t0 = half ? HALFLEN : 1;
        const int t1 = half ? SEQ_LEN : HALFLEN;
        for (int bb = 0; bb < NB; bb++) {
            float r = 0.0f;
            for (int t = t0 + lane; t < t1; t += 32) {
                int tc = tagsg[bb * SEQ_LEN + t];
                int tp = tagsg[bb * SEQ_LEN + t - 1];
                if (maskg[bb * SEQ_LEN + t])
                    r += em0[((size_t)bb * SEQ_LEN + t) * NUM_TAGS + tc]
                       + transitions[tp * NUM_TAGS + tc];
            }
            #pragma unroll
            for (int off = 16; off; off >>= 1)
                r += __shfl_xor_sync(0xffffffffu, r, off);
            if (lane == 0) {
                if (half == 0)
                    r += em0[(size_t)bb * SEQ_LEN * NUM_TAGS + tagsg[bb * SEQ_LEN]];
                g_sc2[grp][half][bb] = r;
            }
        }
    }

    // --- A fragments (tf32). fwd: A=E^T (row m, col k) = T[k][m]; bwd: T[m][k].
    uint32_t A[3][6][4];
    #pragma unroll
    for (int mt = 0; mt < 3; mt++)
        #pragma unroll
        for (int kk = 0; kk < 6; kk++) {
            int r = 16 * mt + g, c = 8 * kk + tig;
            if (half == 0) {
                A[mt][kk][0] = f2tf(__expf(transitions[(c    ) * NUM_TAGS + r    ]));
                A[mt][kk][1] = f2tf(__expf(transitions[(c    ) * NUM_TAGS + r + 8]));
                A[mt][kk][2] = f2tf(__expf(transitions[(c + 4) * NUM_TAGS + r    ]));
                A[mt][kk][3] = f2tf(__expf(transitions[(c + 4) * NUM_TAGS + r + 8]));
            } else {
                A[mt][kk][0] = f2tf(__expf(transitions[(r    ) * NUM_TAGS + c    ]));
                A[mt][kk][1] = f2tf(__expf(transitions[(r + 8) * NUM_TAGS + c    ]));
                A[mt][kk][2] = f2tf(__expf(transitions[(r    ) * NUM_TAGS + c + 4]));
                A[mt][kk][3] = f2tf(__expf(transitions[(r + 8) * NUM_TAGS + c + 4]));
            }
        }

    // --- init state: fwd w = delta_0; bwd v = ones ----------------------------
    for (int idx = lane; idx < NUM_TAGS * NB; idx += 32) {
        int j = idx >> 3, n = idx & 7;
        sW[0][j][n] = half ? 1.0f : ((j == 0) ? 1.0f : 0.0f);
    }
    if (lane < NB) sCi[lane] = 1.0f;
    float Creg = 0.0f;    // valid in lanes 0..7 (lane n holds C_n)
    __syncwarp();

    // --- recursion: 32 chunks x 8 steps ----------------------------------------
    for (int c = 0; c < NCH; c++) {
        if (c + 2 < NCH) {
            uint32_t dstb = (uint32_t)__cvta_generic_to_shared(&sem[(c + 2) % 3][0]);
            int tb2 = TBASE(c + 2);
            for (int i = lane; i < CHUNK * NB * 12; i += 32) {
                int row = i / 12, part = i % 12;
                int u = row >> 3, n = row & 7;
                cp16(dstb + (uint32_t)(((u * NB + n) * EPAD + part * 4) * 4),
                     em0 + ((size_t)n * SEQ_LEN + tb2 + u) * NUM_TAGS + part * 4);
            }
        }
        asm volatile("cp.async.commit_group;");
        asm volatile("cp.async.wait_group 2;");
        __syncwarp();

        const float* eb = sem[c % 3];
        const int tb = TBASE(c);

        int mA = maskg[g * SEQ_LEN + tb + 2 * tig];
        int mB = maskg[g * SEQ_LEN + tb + 2 * tig + 1];
        const bool mall = __all_sync(0xffffffffu, (mA != 0) && (mB != 0));

        float cil0 = sCi[2 * tig], cil1 = sCi[2 * tig + 1];   // fwd fold (per n)
        float cig  = sCi[g];                                   // bwd fold (per n)

        if (!mall) {   // rare: materialize pending scale, then select-based steps
            __syncwarp();
            for (int idx = lane; idx < NUM_TAGS * NB; idx += 32) {
                int j = idx >> 3, n = idx & 7;
                sW[0][j][n] *= sCi[n];
            }
            __syncwarp();
            if (lane < NB) sCi[lane] = 1.0f;
            cil0 = cil1 = cig = 1.0f;
            __syncwarp();
        }

        #pragma unroll
        for (int s = 0; s < CHUNK; s++) {
            const int u  = half ? (CHUNK - 1 - s) : s;   // consumed time offset
            const int rb = s & 1, wb = rb ^ 1;

            // B fragments
            uint32_t bfr[6][2];
            #pragma unroll
            for (int kk = 0; kk < 6; kk++) {
                bfr[kk][0] = __float_as_uint(sW[rb][8 * kk + tig    ][g]);
                bfr[kk][1] = __float_as_uint(sW[rb][8 * kk + tig + 4][g]);
            }
            if (half == 1) {   // bwd: B <- exp(e_t) . B  (k rows, col n=g)
                #pragma unroll
                for (int kk = 0; kk < 6; kk++)
                    #pragma unroll
                    for (int pp = 0; pp < 2; pp++) {
                        int k = 8 * kk + tig + 4 * pp;
                        float x = __expf(eb[(u * NB + g) * EPAD + k]);
                        if (s == 0) x *= cig;
                        bfr[kk][pp] = __float_as_uint(__uint_as_float(bfr[kk][pp]) * x);
                    }
            }

            float acc[3][2][4] = {};
            #pragma unroll
            for (int k2 = 0; k2 < 3; k2++)
                #pragma unroll
                for (int mt = 0; mt < 3; mt++)
                    #pragma unroll
                    for (int hf = 0; hf < 2; hf++)
                        mma_tf32(acc[mt][hf],
                                 A[mt][hf * 3 + k2][0], A[mt][hf * 3 + k2][1],
                                 A[mt][hf * 3 + k2][2], A[mt][hf * 3 + k2][3],
                                 bfr[hf * 3 + k2][0], bfr[hf * 3 + k2][1]);

            int m0 = 1, m1 = 1;
            if (!mall) {
                m0 = maskg[(2 * tig    ) * SEQ_LEN + tb + u];
                m1 = maskg[(2 * tig + 1) * SEQ_LEN + tb + u];
            }

            #pragma unroll
            for (int mt = 0; mt < 3; mt++)
                #pragma unroll
                for (int hh = 0; hh < 2; hh++) {
                    int j = 16 * mt + g + 8 * hh;
                    float d0 = acc[mt][0][2 * hh + 0] + acc[mt][1][2 * hh + 0];
                    float d1 = acc[mt][0][2 * hh + 1] + acc[mt][1][2 * hh + 1];
                    if (half == 0) {   // fwd: * exp(e_t) at D positions
                        float x0 = __expf(eb[(u * NB + 2 * tig    ) * EPAD + j]);
                        float x1 = __expf(eb[(u * NB + 2 * tig + 1) * EPAD + j]);
                        if (s == 0) { x0 *= cil0; x1 *= cil1; }
                        d0 *= x0; d1 *= x1;
                    }
                    if (!mall) {
                        float o0 = sW[rb][j][2 * tig];
                        float o1 = sW[rb][j][2 * tig + 1];
                        d0 = m0 ? d0 : o0;
                        d1 = m1 ? d1 : o1;
                    }
                    *(float2*)&sW[wb][j][2 * tig] = make_float2(d0, d1);
                }
            __syncwarp();
        }

        // lazy per-batch renorm: s_n = W[0][n] > 0; exact once logged
        if (lane < NB) {
            float sv = sW[0][0][lane];
            Creg += __logf(sv);
            sCi[lane] = __fdividef(1.0f, sv);
        }
        __syncwarp();
    }

    // --- publish normalized vec + C ---------------------------------------------
    for (int idx = lane; idx < NUM_TAGS * NB; idx += 32) {
        int j = idx >> 3, n = idx & 7;
        float v = sW[0][j][n] * sCi[n];
        if (half) g_vecB[grp][j][n] = v; else g_vecF[grp][j][n] = v;
    }
    if (lane < NB) g_C2[grp][half][lane] = Creg;

    // --- pair combine; then global mean by the very last finisher ----------------
    unsigned turn = 0;
    if (lane == 0) {
        __threadfence();
        turn = atomicAdd(&g_pair[grp], 1u);
    }
    turn = __shfl_sync(0xffffffffu, turn, 0);
    if (turn == 1) {
        __threadfence();
        int n = lane >> 2, seg = lane & 3;
        float p = 0.0f;
        #pragma unroll
        for (int j = seg * 12; j < seg * 12 + 12; j++)
            p += __ldcg(&g_vecF[grp][j][n]) * __ldcg(&g_vecB[grp][j][n]);
        p += __shfl_xor_sync(0xffffffffu, p, 1);
        p += __shfl_xor_sync(0xffffffffu, p, 2);
        if (seg == 0) {
            float Csum = __ldcg(&g_C2[grp][0][n]) + __ldcg(&g_C2[grp][1][n]);
            float scs  = __ldcg(&g_sc2[grp][0][n]) + __ldcg(&g_sc2[grp][1][n]);
            g_nll[b8 + n] = Csum + __logf(p) - scs;
        }
        unsigned dn = 0;
        if (lane == 0) {
            g_pair[grp] = 0;            // reset for graph replay
            __threadfence();
            dn = atomicAdd(&g_count, 1u);
        }
        dn = __shfl_sync(0xffffffffu, dn, 0);
        if (dn == NGRP - 1) {
            __threadfence();
            float r = 0.0f;
            #pragma unroll
            for (int i = lane; i < BATCH; i += 32)
                r += __ldcg(&g_nll[i]);
            #pragma unroll
            for (int off = 16; off; off >>= 1)
                r += __shfl_xor_sync(0xffffffffu, r, off);
            if (lane == 0) {
                out[0] = r * (1.0f / (float)BATCH);
                g_count = 0;            // reset for graph replay
            }
        }
    }
    #undef TBASE
}

extern "C" void kernel_launch(void* const* d_in, const int* in_sizes, int n_in,
                              void* d_out, int out_size)
{
    const float* emissions   = (const float*)d_in[0];
    const float* transitions = (const float*)d_in[1];
    const int*   tags        = (const int*)d_in[2];
    const int*   mask        = (const int*)d_in[3];
    float*       out         = (float*)d_out;

    crf_mma2_kernel<<<2 * NGRP, 32>>>(emissions, transitions, tags, mask, out);
}

// round 14
// speedup vs baseline: 2.4490x; 1.9273x over previous
#include <cuda_runtime.h>
#include <cuda_bf16.h>
#include <cstdint>

#define NUM_TAGS 48
#define SEQ_LEN  512
#define BATCH    1024
#define CHUNK    8
#define NCHUNK   (SEQ_LEN / CHUNK)   // 64

__device__ float    g_nll[BATCH];
__device__ unsigned g_count = 0;

// bf16x2 packed FMA: d = a*b + d (lane-wise on two bf16)
__device__ __forceinline__ void hfma2(uint32_t& d, uint32_t a, uint32_t b) {
    asm("fma.rn.bf16x2 %0, %1, %2, %0;" : "+r"(d) : "r"(a), "r"(b));
}
// pack two fp32 into bf16x2 (lo -> low half, hi -> high half)
__device__ __forceinline__ uint32_t pack_bf2(float lo, float hi) {
    uint32_t r;
    asm("cvt.rn.bf16x2.f32 %0, %1, %2;" : "=r"(r) : "f"(hi), "f"(lo));
    return r;
}
__device__ __forceinline__ float bf_lo(uint32_t u) { return __uint_as_float(u << 16); }
__device__ __forceinline__ float bf_hi(uint32_t u) { return __uint_as_float(u & 0xFFFF0000u); }
__device__ __forceinline__ uint16_t f2bf(float f) {
    uint16_t r;
    asm("cvt.rn.bf16.f32 %0, %1;" : "=h"(r) : "f"(f));
    return r;
}

__device__ __forceinline__ void cp16(uint32_t saddr, const void* g) {
    asm volatile("cp.async.cg.shared.global [%0], [%1], 16;" :: "r"(saddr), "l"(g));
}

// One warp (one CTA) per batch element. Alpha in shared as 48 bf16 (96 B, one
// 128-B line). Dot products run NATIVELY on packed bf16x2 via HFMA2 (no unpack
// ALU). K split by h=lane>>4, combined with one fp32 shfl per output. Lazy
// per-chunk renorm; fast path has no WARPSYNC (full-mask shfl anchors
// convergence; pair lanes store bit-identical duplicates).
__global__ __launch_bounds__(32)
void crf_fused_kernel(const float* __restrict__ emissions,
                      const float* __restrict__ transitions,
                      const int*   __restrict__ tags,
                      const int*   __restrict__ mask,
                      float*       __restrict__ out)
{
    const int lane = threadIdx.x;
    const int b    = blockIdx.x;
    const int h    = lane >> 4;     // K half: tags [24h, 24h+24)
    const int q    = lane & 15;     // owned output triple {3q,3q+1,3q+2}
    const int j0   = 3 * q;

    __shared__ __align__(128) uint32_t swb16[2][32];          // 48 bf16 + pad, x2 buffers
    __shared__ __align__(16)  float sem[3][CHUNK * NUM_TAGS]; // emission chunks
    __shared__ int stags[SEQ_LEN];
    __shared__ int smask[SEQ_LEN];

    const float* em_b   = emissions + (size_t)b * SEQ_LEN * NUM_TAGS;
    const int*   tags_b = tags + b * SEQ_LEN;
    const int*   mask_b = mask + b * SEQ_LEN;

    // --- stage emission chunks 0,1 -------------------------------------------
    #pragma unroll
    for (int pc = 0; pc < 2; pc++) {
        uint32_t dst = (uint32_t)__cvta_generic_to_shared(&sem[pc][0]);
        const float* src = em_b + (size_t)pc * CHUNK * NUM_TAGS;
        #pragma unroll
        for (int r = 0; r < 3; r++)
            cp16(dst + lane * 16 + r * 512, src + lane * 4 + r * 128);
        asm volatile("cp.async.commit_group;");
    }

    // --- tags / mask to shared ---------------------------------------------------
    #pragma unroll
    for (int r = 0; r < 4; r++) {
        ((int4*)stags)[lane + 32 * r] = ((const int4*)tags_b)[lane + 32 * r];
        ((int4*)smask)[lane + 32 * r] = ((const int4*)mask_b)[lane + 32 * r];
    }

    // --- E = exp(T) as bf16x2: 3 owned cols x 12 input-pairs (this K half) --------
    const int i0 = 24 * h;
    uint32_t Ec[3][12];
    #pragma unroll
    for (int c = 0; c < 3; c++)
        #pragma unroll
        for (int k = 0; k < 12; k++)
            Ec[c][k] = pack_bf2(__expf(transitions[(i0 + 2 * k    ) * NUM_TAGS + j0 + c]),
                                __expf(transitions[(i0 + 2 * k + 1) * NUM_TAGS + j0 + c]));

    // --- init alphas: only tag 0 live (bf16(1.0)=0x3F80 low half of word 0) --------
    float w0 = (q == 0) ? 1.0f : 0.0f;
    float w1 = 0.0f, w2 = 0.0f;
    if (lane < 24) swb16[0][lane] = (lane == 0) ? 0x00003F80u : 0u;
    __syncwarp();

    // --- gold-path score (overlaps staged-chunk latency) ----------------------------
    float sc = 0.0f;
    #pragma unroll 4
    for (int t = 1 + lane; t < SEQ_LEN; t += 32) {
        int tc = stags[t], tp = stags[t - 1];
        if (smask[t])
            sc += em_b[(size_t)t * NUM_TAGS + tc] + transitions[tp * NUM_TAGS + tc];
    }
    #pragma unroll
    for (int off = 16; off; off >>= 1)
        sc += __shfl_xor_sync(0xffffffffu, sc, off);

    // --- forward recursion: 64 chunks x 8 steps --------------------------------------
    float C = 0.0f;
    float carry_inv = 1.0f;   // pending renorm scale (exact once logged)

    for (int c = 0; c < NCHUNK; c++) {
        if (c + 2 < NCHUNK) {
            uint32_t dst = (uint32_t)__cvta_generic_to_shared(&sem[(c + 2) % 3][0]);
            const float* src = em_b + (size_t)(c + 2) * CHUNK * NUM_TAGS;
            #pragma unroll
            for (int r = 0; r < 3; r++)
                cp16(dst + lane * 16 + r * 512, src + lane * 4 + r * 128);
        }
        asm volatile("cp.async.commit_group;");
        asm volatile("cp.async.wait_group 2;");
        __syncwarp();

        const float* eb = sem[c % 3];

        // hoist emission exps (off the recurrence chain)
        float eE[CHUNK][3];
        #pragma unroll
        for (int u = 0; u < CHUNK; u++) {
            eE[u][0] = __expf(eb[u * NUM_TAGS + j0]);
            eE[u][1] = __expf(eb[u * NUM_TAGS + j0 + 1]);
            eE[u][2] = __expf(eb[u * NUM_TAGS + j0 + 2]);
        }

        const int4 ma  = ((const int4*)(smask + c * CHUNK))[0];
        const int4 mbq = ((const int4*)(smask + c * CHUNK))[1];
        const int mall = ma.x & ma.y & ma.z & ma.w & mbq.x & mbq.y & mbq.z & mbq.w;

        if (mall) {
            // fast path: fold pending scale into step 0's emission factor
            eE[0][0] *= carry_inv; eE[0][1] *= carry_inv; eE[0][2] *= carry_inv;

            #pragma unroll
            for (int u = 0; u < CHUNK; u++) {
                // alpha: this half's 24 bf16 = 48 B = 3 LDS.128 (one 128-B line)
                const uint32_t* wln = &swb16[u & 1][h * 12];
                uint4 A0 = *(const uint4*)(wln);
                uint4 A1 = *(const uint4*)(wln + 4);
                uint4 A2 = *(const uint4*)(wln + 8);
                uint32_t A[12] = {A0.x, A0.y, A0.z, A0.w,
                                  A1.x, A1.y, A1.z, A1.w,
                                  A2.x, A2.y, A2.z, A2.w};

                // packed bf16x2 dots: 2 chains x 6 per column, no unpack
                uint32_t pa[3] = {0, 0, 0}, pb[3] = {0, 0, 0};
                #pragma unroll
                for (int k = 0; k < 6; k++) {
                    #pragma unroll
                    for (int cc = 0; cc < 3; cc++) {
                        hfma2(pa[cc], A[k],     Ec[cc][k]);
                        hfma2(pb[cc], A[k + 6], Ec[cc][k + 6]);
                    }
                }
                float d[3];
                #pragma unroll
                for (int cc = 0; cc < 3; cc++) {
                    float dd = (bf_lo(pa[cc]) + bf_hi(pa[cc]))
                             + (bf_lo(pb[cc]) + bf_hi(pb[cc]));
                    dd += __shfl_xor_sync(0xffffffffu, dd, 16);   // combine halves
                    d[cc] = dd * eE[u][cc];
                }
                w0 = d[0]; w1 = d[1]; w2 = d[2];
                uint16_t* wd = (uint16_t*)swb16[(u & 1) ^ 1];
                wd[j0]     = f2bf(w0);      // all lanes store; pair duplicates identical
                wd[j0 + 1] = f2bf(w1);
                wd[j0 + 2] = f2bf(w2);
                asm volatile("" ::: "memory");
            }
        } else {
            // slow path (general mask): apply pending scale, then select-based steps
            w0 *= carry_inv; w1 *= carry_inv; w2 *= carry_inv;
            carry_inv = 1.0f;
            {
                uint16_t* wd = (uint16_t*)swb16[0];
                wd[j0] = f2bf(w0); wd[j0 + 1] = f2bf(w1); wd[j0 + 2] = f2bf(w2);
            }
            __syncwarp();

            #pragma unroll
            for (int u = 0; u < CHUNK; u++) {
                const uint32_t* wln = &swb16[u & 1][h * 12];
                uint4 A0 = *(const uint4*)(wln);
                uint4 A1 = *(const uint4*)(wln + 4);
                uint4 A2 = *(const uint4*)(wln + 8);
                uint32_t A[12] = {A0.x, A0.y, A0.z, A0.w,
                                  A1.x, A1.y, A1.z, A1.w,
                                  A2.x, A2.y, A2.z, A2.w};

                uint32_t pa[3] = {0, 0, 0}, pb[3] = {0, 0, 0};
                #pragma unroll
                for (int k = 0; k < 6; k++) {
                    #pragma unroll
                    for (int cc = 0; cc < 3; cc++) {
                        hfma2(pa[cc], A[k],     Ec[cc][k]);
                        hfma2(pb[cc], A[k + 6], Ec[cc][k + 6]);
                    }
                }
                int m = smask[c * CHUNK + u];
                float nv[3];
                #pragma unroll
                for (int cc = 0; cc < 3; cc++) {
                    float dd = (bf_lo(pa[cc]) + bf_hi(pa[cc]))
                             + (bf_lo(pb[cc]) + bf_hi(pb[cc]));
                    dd += __shfl_xor_sync(0xffffffffu, dd, 16);
                    nv[cc] = dd * eE[u][cc];
                }
                w0 = m ? nv[0] : w0;
                w1 = m ? nv[1] : w1;
                w2 = m ? nv[2] : w2;
                uint16_t* wd = (uint16_t*)swb16[(u & 1) ^ 1];
                wd[j0] = f2bf(w0); wd[j0 + 1] = f2bf(w1); wd[j0 + 2] = f2bf(w2);
                __syncwarp();
            }
        }

        // lazy renorm: scale by alpha[0] (>0 always); exact algebra once logged
        float s = __shfl_sync(0xffffffffu, w0, 0);
        C += __logf(s);
        carry_inv = __fdividef(1.0f, s);
    }

    // --- final partition: logZ = C + log( (sum w) * carry_inv ) ------------------------
    float v = (h == 0) ? (w0 + w1 + w2) : 0.0f;
    #pragma unroll
    for (int off = 16; off; off >>= 1)
        v += __shfl_xor_sync(0xffffffffu, v, off);
    if (lane == 0) {
        float logZ  = C + __logf(v * carry_inv);
        float score = sc + em_b[stags[0]];           // emit[0] always counted
        g_nll[b] = logZ - score;
    }

    // --- fused mean-reduce: last CTA does the deterministic sum ------------------------
    unsigned done = 0;
    if (lane == 0) {
        __threadfence();
        done = atomicAdd(&g_count, 1u);
    }
    done = __shfl_sync(0xffffffffu, done, 0);
    if (done == BATCH - 1) {
        __threadfence();
        float r = 0.0f;
        #pragma unroll
        for (int i = lane; i < BATCH; i += 32)
            r += __ldcg(&g_nll[i]);
        #pragma unroll
        for (int off = 16; off; off >>= 1)
            r += __shfl_xor_sync(0xffffffffu, r, off);
        if (lane == 0) {
            out[0] = r * (1.0f / (float)BATCH);
            g_count = 0;   // reset for next graph replay
        }
    }
}

extern "C" void kernel_launch(void* const* d_in, const int* in_sizes, int n_in,
                              void* d_out, int out_size)
{
    const float* emissions   = (const float*)d_in[0];
    const float* transitions = (const float*)d_in[1];
    const int*   tags        = (const int*)d_in[2];
    const int*   mask        = (const int*)d_in[3];
    float*       out         = (float*)d_out;

    crf_fused_kernel<<<BATCH, 32>>>(emissions, transitions, tags, mask, out);
}